// round 4
// baseline (speedup 1.0000x reference)
#include <cuda_runtime.h>

#define Fq   20
#define Dq   16
#define NBq  500000
#define Bq   4096
#define NIq  190          // F*(F-1)/2
#define FDq  320          // F*D

// Device-global scratch (accessed through float4 -> align 16)
__device__ __align__(16) float g_W12T[NIq * FDq];   // (w1@w2)^T : [j][k]
__device__ __align__(16) float g_W[Bq * NIq];       // z@w1@w2 : [b][j]
__device__ __align__(16) float g_CT0[NBq * Dq];     // codebook @ W_top : 32 MB
__device__ __align__(16) float g_CT1[NBq * Dq];     // codebook @ W_bot : 32 MB

#define W12_TILES 60                       // 10 x 6 tiles of 32x32
#define ROWS_PER_CT_BLOCK 1024             // 256 threads x 4 rows
#define CT_BLOCKS ((NBq + ROWS_PER_CT_BLOCK - 1) / ROWS_PER_CT_BLOCK)  // 489

// packed fp32x2 FMA (element-wise, exact fp32 rounding)
union F2U { float2 f; unsigned long long u; };
__device__ __forceinline__ float2 ffma2(float2 a, float2 b, float2 c) {
    F2U A, B, C; A.f = a; B.f = b; C.f = c;
    asm("fma.rn.f32x2 %0, %1, %2, %0;" : "+l"(C.u) : "l"(A.u), "l"(B.u));
    return C.f;
}

// ---------------------------------------------------------------------------
// K1 (fused, grid-split):
//   blocks [0,60):  tiled GEMM  W12T = (w1 @ w2)^T
//   blocks [60,..): codebook transform CT0/CT1, 4 rows/thread (W reused in regs)
// ---------------------------------------------------------------------------
__global__ __launch_bounds__(256) void k_pre(
    const float* __restrict__ w1,        // (320,320)
    const float* __restrict__ w2,        // (320,190)
    const float* __restrict__ Wt,        // (32,16)
    const float* __restrict__ codebook)  // (500000,16)
{
    if (blockIdx.x < W12_TILES) {
        __shared__ float As[32][33];
        __shared__ float Bs[32][33];
        const int tile = blockIdx.x;
        const int ti = tile / 6, tj = tile % 6;
        const int row0 = ti * 32, col0 = tj * 32;
        const int tid = threadIdx.x;
        const int tx = tid & 15, ty = tid >> 4;
        float a00 = 0.f, a01 = 0.f, a10 = 0.f, a11 = 0.f;
        for (int k0 = 0; k0 < FDq; k0 += 32) {
            #pragma unroll
            for (int i = tid; i < 32 * 32; i += 256) {
                int r = i >> 5, c = i & 31;
                As[r][c] = w1[(row0 + r) * FDq + k0 + c];
                int cb = col0 + c;
                Bs[r][c] = (cb < NIq) ? w2[(k0 + r) * NIq + cb] : 0.f;
            }
            __syncthreads();
            #pragma unroll
            for (int k = 0; k < 32; k++) {
                float x0 = As[ty * 2][k],  x1 = As[ty * 2 + 1][k];
                float y0 = Bs[k][tx * 2],  y1 = Bs[k][tx * 2 + 1];
                a00 += x0 * y0; a01 += x0 * y1;
                a10 += x1 * y0; a11 += x1 * y1;
            }
            __syncthreads();
        }
        int i0 = row0 + ty * 2, j0 = col0 + tx * 2;
        if (j0     < NIq) { g_W12T[ j0      * FDq + i0] = a00; g_W12T[ j0      * FDq + i0 + 1] = a10; }
        if (j0 + 1 < NIq) { g_W12T[(j0 + 1) * FDq + i0] = a01; g_W12T[(j0 + 1) * FDq + i0 + 1] = a11; }
    } else {
        // ---- codebook transform: 4 rows per thread, W reused across rows ----
        __shared__ __align__(16) float Ws[32 * 16];
        const int tid = threadIdx.x;
        Ws[tid]       = Wt[tid];
        Ws[tid + 256] = Wt[tid + 256];
        __syncthreads();

        const int base = (blockIdx.x - W12_TILES) * ROWS_PER_CT_BLOCK;
        int   rows[4];
        bool  valid[4];
        float c[4][16];
        #pragma unroll
        for (int rr = 0; rr < 4; rr++) {
            int r = base + tid + 256 * rr;
            rows[rr] = r;
            valid[rr] = (r < NBq);
            if (valid[rr]) {
                const float4* cbv = (const float4*)(codebook + r * Dq);
                #pragma unroll
                for (int q = 0; q < 4; q++) {
                    float4 v = cbv[q];
                    c[rr][q * 4] = v.x; c[rr][q * 4 + 1] = v.y;
                    c[rr][q * 4 + 2] = v.z; c[rr][q * 4 + 3] = v.w;
                }
            }
        }

        const float4* Wv = (const float4*)Ws;   // [32 rows][4 quads]
        #pragma unroll
        for (int dq = 0; dq < 4; dq++) {
            float4 s0[4], s1[4];
            #pragma unroll
            for (int rr = 0; rr < 4; rr++) {
                s0[rr] = make_float4(0.f, 0.f, 0.f, 0.f);
                s1[rr] = make_float4(0.f, 0.f, 0.f, 0.f);
            }
            #pragma unroll
            for (int k = 0; k < 16; k++) {
                float4 wt = Wv[k * 4 + dq];
                float4 wb = Wv[(16 + k) * 4 + dq];
                #pragma unroll
                for (int rr = 0; rr < 4; rr++) {
                    float ck = c[rr][k];
                    s0[rr].x += ck * wt.x; s0[rr].y += ck * wt.y;
                    s0[rr].z += ck * wt.z; s0[rr].w += ck * wt.w;
                    s1[rr].x += ck * wb.x; s1[rr].y += ck * wb.y;
                    s1[rr].z += ck * wb.z; s1[rr].w += ck * wb.w;
                }
            }
            #pragma unroll
            for (int rr = 0; rr < 4; rr++) {
                if (valid[rr]) {
                    ((float4*)(g_CT0 + rows[rr] * Dq))[dq] = s0[rr];
                    ((float4*)(g_CT1 + rows[rr] * Dq))[dq] = s1[rr];
                }
            }
        }
    }
}

// ---------------------------------------------------------------------------
// K2: g_W = Z @ W12 via W12T rows; packed f32x2 FMA over k-pairs.
// 256 blocks x 16 batches; thread j owns column j for all 16 batches.
// ---------------------------------------------------------------------------
#define TBq 16
__global__ __launch_bounds__(192) void k_senet(const float* __restrict__ z) {
    __shared__ __align__(16) float zs[TBq * FDq];   // 20 KB
    const int b0 = blockIdx.x * TBq;
    const int tid = threadIdx.x;
    {
        const float4* src = (const float4*)(z + b0 * FDq);
        float4* dst = (float4*)zs;
        for (int i = tid; i < TBq * FDq / 4; i += 192) dst[i] = src[i];
    }
    __syncthreads();
    const int j = tid;
    if (j >= NIq) return;

    float2 acc[TBq];
    #pragma unroll
    for (int b = 0; b < TBq; b++) acc[b] = make_float2(0.f, 0.f);

    const float4* wp = (const float4*)(g_W12T + j * FDq);
    #pragma unroll 4
    for (int k0 = 0; k0 < FDq / 4; k0++) {
        float4 w = wp[k0];                 // L2-resident, reused by all blocks
        float2 w01 = make_float2(w.x, w.y);
        float2 w23 = make_float2(w.z, w.w);
        #pragma unroll
        for (int b = 0; b < TBq; b++) {
            float4 v = *(const float4*)(zs + b * FDq + k0 * 4);  // LDS broadcast
            acc[b] = ffma2(make_float2(v.x, v.y), w01, acc[b]);
            acc[b] = ffma2(make_float2(v.z, v.w), w23, acc[b]);
        }
    }
    #pragma unroll
    for (int b = 0; b < TBq; b++)
        g_W[(b0 + b) * NIq + j] = acc[b].x + acc[b].y;
}

// ---------------------------------------------------------------------------
// K3: combine, 2 batches per block (2048 blocks).
//  Phase 1: quad per pair: gather CT0[i0]+CT1[i1] (float4), scale, STS.
//  Phase 2: thread per (f,d): sum 19 pair contributions.
// ---------------------------------------------------------------------------
#define BPB 2
__global__ __launch_bounds__(256) void k_combine(
    const int* __restrict__ hash_idx,    // (2, B, NI)
    const int* __restrict__ inter,       // (20, 19)
    float*     __restrict__ out)         // (B, 20, 16)
{
    __shared__ float ws[BPB * NIq];
    __shared__ __align__(16) float embw[BPB][NIq * 20];   // 2 x 15.2 KB
    __shared__ int idxs[Fq * (Fq - 1)];

    const int b0  = blockIdx.x * BPB;
    const int tid = threadIdx.x;

    for (int i = tid; i < BPB * NIq; i += 256) ws[i] = g_W[b0 * NIq + i];
    for (int i = tid; i < Fq * (Fq - 1); i += 256) idxs[i] = inter[i];
    __syncthreads();

    const float4* ct0 = (const float4*)g_CT0;
    const float4* ct1 = (const float4*)g_CT1;

    for (int t = tid; t < BPB * NIq * 4; t += 256) {
        int bb  = t / (NIq * 4);
        int rem = t - bb * (NIq * 4);
        int j = rem >> 2, q = rem & 3;
        const int* h0 = hash_idx + (b0 + bb) * NIq;
        const int* h1 = hash_idx + Bq * NIq + (b0 + bb) * NIq;
        int i0 = h0[j], i1 = h1[j];
        float4 a = ct0[i0 * 4 + q];
        float4 c = ct1[i1 * 4 + q];
        float w = ws[bb * NIq + j];
        float4 v;
        v.x = (a.x + c.x) * w; v.y = (a.y + c.y) * w;
        v.z = (a.z + c.z) * w; v.w = (a.w + c.w) * w;
        *((float4*)(&embw[bb][j * 20 + q * 4])) = v;
    }
    __syncthreads();

    for (int o = tid; o < BPB * Fq * Dq; o += 256) {
        int bb = o / (Fq * Dq);
        int oo = o - bb * (Fq * Dq);
        int f = oo >> 4, d = oo & 15;
        const int* row = idxs + f * (Fq - 1);
        float s = 0.f;
        #pragma unroll
        for (int p = 0; p < Fq - 1; p++)
            s += embw[bb][row[p] * 20 + d];
        out[(b0 + bb) * Fq * Dq + oo] = s;
    }
}

// ---------------------------------------------------------------------------
extern "C" void kernel_launch(void* const* d_in, const int* in_sizes, int n_in,
                              void* d_out, int out_size) {
    const float* origin   = (const float*)d_in[0];  // (B, F, D)
    const float* codebook = (const float*)d_in[1];  // (NB, D)
    const float* Wt       = (const float*)d_in[2];  // (32, 16)
    const float* w1       = (const float*)d_in[3];  // (320, 320)
    const float* w2       = (const float*)d_in[4];  // (320, 190)
    const int*   hash     = (const int*)d_in[5];    // (2, B, NI)
    const int*   inter    = (const int*)d_in[6];    // (20, 19)
    float*       out      = (float*)d_out;

    k_pre<<<W12_TILES + CT_BLOCKS, 256>>>(w1, w2, Wt, codebook);
    k_senet<<<Bq / TBq, 192>>>(origin);
    k_combine<<<Bq / BPB, 256>>>(hash, inter, out);
}

// round 5
// speedup vs baseline: 1.0376x; 1.0376x over previous
#include <cuda_runtime.h>

#define Fq   20
#define Dq   16
#define NBq  500000
#define Bq   4096
#define NIq  190          // F*(F-1)/2
#define FDq  320          // F*D

// Device-global scratch (float4-accessed -> align 16)
__device__ __align__(16) float g_W12[FDq * NIq];    // w1@w2, natural [k][j]
__device__ __align__(16) float g_W[Bq * NIq];       // z@w1@w2 : [b][j]
__device__ __align__(16) float g_CT0[NBq * Dq];     // codebook @ W_top : 32 MB
__device__ __align__(16) float g_CT1[NBq * Dq];     // codebook @ W_bot : 32 MB

#define W12_TILES 60                       // 10 x 6 tiles of 32x32
#define CT_BLOCKS ((NBq + 255) / 256)      // 1954, 256 rows/block

// packed fp32x2 FMA (element-wise, exact fp32 rounding)
union F2U { float2 f; unsigned long long u; };
__device__ __forceinline__ float2 ffma2(float2 a, float2 b, float2 c) {
    F2U A, B, C; A.f = a; B.f = b; C.f = c;
    asm("fma.rn.f32x2 %0, %1, %2, %0;" : "+l"(C.u) : "l"(A.u), "l"(B.u));
    return C.f;
}

// ---------------------------------------------------------------------------
// K1 (fused, grid-split):
//   blocks [0,60):  tiled GEMM  g_W12 = w1 @ w2   (natural [k][j] layout)
//   blocks [60,..): codebook transform CT0/CT1, f32x2, 1 row/thread
// ---------------------------------------------------------------------------
__global__ __launch_bounds__(256) void k_pre(
    const float* __restrict__ w1,        // (320,320)
    const float* __restrict__ w2,        // (320,190)
    const float* __restrict__ Wt,        // (32,16)
    const float* __restrict__ codebook)  // (500000,16)
{
    if (blockIdx.x < W12_TILES) {
        __shared__ float As[32][33];
        __shared__ float Bs[32][33];
        const int tile = blockIdx.x;
        const int ti = tile / 6, tj = tile % 6;
        const int row0 = ti * 32, col0 = tj * 32;
        const int tid = threadIdx.x;
        const int tx = tid & 15, ty = tid >> 4;
        float a00 = 0.f, a01 = 0.f, a10 = 0.f, a11 = 0.f;
        for (int k0 = 0; k0 < FDq; k0 += 32) {
            #pragma unroll
            for (int i = tid; i < 32 * 32; i += 256) {
                int r = i >> 5, c = i & 31;
                As[r][c] = w1[(row0 + r) * FDq + k0 + c];
                int cb = col0 + c;
                Bs[r][c] = (cb < NIq) ? w2[(k0 + r) * NIq + cb] : 0.f;
            }
            __syncthreads();
            #pragma unroll
            for (int k = 0; k < 32; k++) {
                float x0 = As[ty * 2][k],  x1 = As[ty * 2 + 1][k];
                float y0 = Bs[k][tx * 2],  y1 = Bs[k][tx * 2 + 1];
                a00 += x0 * y0; a01 += x0 * y1;
                a10 += x1 * y0; a11 += x1 * y1;
            }
            __syncthreads();
        }
        int i0 = row0 + ty * 2, j0 = col0 + tx * 2;
        if (j0 < NIq) {
            g_W12[ i0      * NIq + j0] = a00;
            g_W12[(i0 + 1) * NIq + j0] = a10;
        }
        if (j0 + 1 < NIq) {
            g_W12[ i0      * NIq + j0 + 1] = a01;
            g_W12[(i0 + 1) * NIq + j0 + 1] = a11;
        }
    } else {
        // ---- codebook transform, f32x2, one row per thread ----
        __shared__ __align__(16) float Ws[32 * 16];
        const int tid = threadIdx.x;
        Ws[tid]       = Wt[tid];
        Ws[tid + 256] = Wt[tid + 256];
        __syncthreads();
        const int r = (blockIdx.x - W12_TILES) * 256 + tid;
        if (r >= NBq) return;

        float2 cc[16];                           // (c_k, c_k) packed
        {
            const float4* cbv = (const float4*)(codebook + r * Dq);
            #pragma unroll
            for (int q = 0; q < 4; q++) {
                float4 v = cbv[q];
                cc[q * 4]     = make_float2(v.x, v.x);
                cc[q * 4 + 1] = make_float2(v.y, v.y);
                cc[q * 4 + 2] = make_float2(v.z, v.z);
                cc[q * 4 + 3] = make_float2(v.w, v.w);
            }
        }

        // pass 0: CT0 (W rows 0..15), pass 1: CT1 (W rows 16..31)
        #pragma unroll
        for (int pass = 0; pass < 2; pass++) {
            float2 s[8];
            #pragma unroll
            for (int p = 0; p < 8; p++) s[p] = make_float2(0.f, 0.f);
            #pragma unroll
            for (int k = 0; k < 16; k++) {
                const float4* wrow = (const float4*)(Ws + (pass * 16 + k) * 16);
                float2 ck = cc[k];
                #pragma unroll
                for (int q = 0; q < 4; q++) {
                    float4 wv = wrow[q];
                    s[q * 2]     = ffma2(ck, make_float2(wv.x, wv.y), s[q * 2]);
                    s[q * 2 + 1] = ffma2(ck, make_float2(wv.z, wv.w), s[q * 2 + 1]);
                }
            }
            float* dst = (pass == 0 ? g_CT0 : g_CT1) + r * Dq;
            #pragma unroll
            for (int q = 0; q < 4; q++)
                ((float4*)dst)[q] = make_float4(s[q * 2].x, s[q * 2].y,
                                                s[q * 2 + 1].x, s[q * 2 + 1].y);
        }
    }
}

// ---------------------------------------------------------------------------
// K2: g_W = Z @ W12.  256 blocks x 16 batches, thread j owns column j.
//  - W12 chunk (64 k x 190 j) staged to smem with coalesced float4 loads
//  - z staged transposed [k][b] so batch-pairs are contiguous -> ffma2
// ---------------------------------------------------------------------------
#define TBq 16
__global__ __launch_bounds__(192) void k_senet(const float* __restrict__ z) {
    __shared__ __align__(16) float zsT[FDq * TBq];   // [k][b], 20 KB
    __shared__ __align__(16) float wsm[64 * NIq];    // 48.6 KB
    const int b0  = blockIdx.x * TBq;
    const int tid = threadIdx.x;

    {   // transpose-stage z: read float4, scatter 4 scalars (same b per quad)
        const float4* src = (const float4*)(z + b0 * FDq);
        for (int i = tid; i < TBq * FDq / 4; i += 192) {
            float4 v = src[i];
            int e = i * 4;
            int b = e / FDq;
            int k = e - b * FDq;
            zsT[ k      * TBq + b] = v.x;
            zsT[(k + 1) * TBq + b] = v.y;
            zsT[(k + 2) * TBq + b] = v.z;
            zsT[(k + 3) * TBq + b] = v.w;
        }
    }

    const int j = tid;
    float2 acc[TBq / 2];
    #pragma unroll
    for (int bp = 0; bp < TBq / 2; bp++) acc[bp] = make_float2(0.f, 0.f);

    for (int kc = 0; kc < FDq; kc += 64) {
        __syncthreads();                             // covers zsT on first iter
        const float4* wsrc = (const float4*)(g_W12 + kc * NIq);
        for (int i = tid; i < 64 * NIq / 4; i += 192)
            ((float4*)wsm)[i] = wsrc[i];             // coalesced stage
        __syncthreads();
        if (j < NIq) {
            #pragma unroll 4
            for (int k = 0; k < 64; k++) {
                float  w  = wsm[k * NIq + j];        // conflict-free scalar LDS
                float2 w2 = make_float2(w, w);
                const float2* zp = (const float2*)(zsT + (kc + k) * TBq);
                #pragma unroll
                for (int bp = 0; bp < TBq / 2; bp++)
                    acc[bp] = ffma2(zp[bp], w2, acc[bp]);   // LDS.64 broadcast
            }
        }
    }
    if (j < NIq) {
        #pragma unroll
        for (int bp = 0; bp < TBq / 2; bp++) {
            g_W[(b0 + 2 * bp)     * NIq + j] = acc[bp].x;
            g_W[(b0 + 2 * bp + 1) * NIq + j] = acc[bp].y;
        }
    }
}

// ---------------------------------------------------------------------------
// K3: combine, 2 batches per block (2048 blocks).
// ---------------------------------------------------------------------------
#define BPB 2
__global__ __launch_bounds__(256) void k_combine(
    const int* __restrict__ hash_idx,    // (2, B, NI)
    const int* __restrict__ inter,       // (20, 19)
    float*     __restrict__ out)         // (B, 20, 16)
{
    __shared__ float ws[BPB * NIq];
    __shared__ __align__(16) float embw[BPB][NIq * 20];
    __shared__ int idxs[Fq * (Fq - 1)];

    const int b0  = blockIdx.x * BPB;
    const int tid = threadIdx.x;

    for (int i = tid; i < BPB * NIq; i += 256) ws[i] = g_W[b0 * NIq + i];
    for (int i = tid; i < Fq * (Fq - 1); i += 256) idxs[i] = inter[i];
    __syncthreads();

    const float4* ct0 = (const float4*)g_CT0;
    const float4* ct1 = (const float4*)g_CT1;

    for (int t = tid; t < BPB * NIq * 4; t += 256) {
        int bb  = t / (NIq * 4);
        int rem = t - bb * (NIq * 4);
        int j = rem >> 2, q = rem & 3;
        const int* h0 = hash_idx + (b0 + bb) * NIq;
        const int* h1 = hash_idx + Bq * NIq + (b0 + bb) * NIq;
        int i0 = h0[j], i1 = h1[j];
        float4 a = ct0[i0 * 4 + q];
        float4 c = ct1[i1 * 4 + q];
        float w = ws[bb * NIq + j];
        float4 v;
        v.x = (a.x + c.x) * w; v.y = (a.y + c.y) * w;
        v.z = (a.z + c.z) * w; v.w = (a.w + c.w) * w;
        *((float4*)(&embw[bb][j * 20 + q * 4])) = v;
    }
    __syncthreads();

    for (int o = tid; o < BPB * Fq * Dq; o += 256) {
        int bb = o / (Fq * Dq);
        int oo = o - bb * (Fq * Dq);
        int f = oo >> 4, d = oo & 15;
        const int* row = idxs + f * (Fq - 1);
        float s = 0.f;
        #pragma unroll
        for (int p = 0; p < Fq - 1; p++)
            s += embw[bb][row[p] * 20 + d];
        out[(b0 + bb) * Fq * Dq + oo] = s;
    }
}

// ---------------------------------------------------------------------------
extern "C" void kernel_launch(void* const* d_in, const int* in_sizes, int n_in,
                              void* d_out, int out_size) {
    const float* origin   = (const float*)d_in[0];  // (B, F, D)
    const float* codebook = (const float*)d_in[1];  // (NB, D)
    const float* Wt       = (const float*)d_in[2];  // (32, 16)
    const float* w1       = (const float*)d_in[3];  // (320, 320)
    const float* w2       = (const float*)d_in[4];  // (320, 190)
    const int*   hash     = (const int*)d_in[5];    // (2, B, NI)
    const int*   inter    = (const int*)d_in[6];    // (20, 19)
    float*       out      = (float*)d_out;

    k_pre<<<W12_TILES + CT_BLOCKS, 256>>>(w1, w2, Wt, codebook);
    k_senet<<<Bq / TBq, 192>>>(origin);
    k_combine<<<Bq / BPB, 256>>>(hash, inter, out);
}

// round 6
// speedup vs baseline: 1.1475x; 1.1059x over previous
#include <cuda_runtime.h>

#define Fq   20
#define Dq   16
#define NBq  500000
#define Bq   4096
#define NIq  190          // F*(F-1)/2
#define NJP  192          // NIq padded
#define FDq  320          // F*D

// Device-global scratch (float4-accessed -> align 16)
__device__ __align__(16) float g_W12[FDq * NJP];    // w1@w2, [k][j] padded to 192
__device__ __align__(16) float g_W[Bq * NIq];       // z@w1@w2 : [b][j]
__device__ __align__(16) float g_CT0[NBq * Dq];     // codebook @ W_top : 32 MB
__device__ __align__(16) float g_CT1[NBq * Dq];     // codebook @ W_bot : 32 MB

// W_transform in constant memory: rows [32][16] as float4 quads
__constant__ float4 c_W4[128];

#define W12_TILES 60                       // 10 x 6 tiles of 32x32
#define CT_BLOCKS ((NBq + 255) / 256)      // 1954, 256 rows/block

// packed fp32x2 FMA (element-wise, exact fp32 rounding)
union F2U { float2 f; unsigned long long u; };
__device__ __forceinline__ float2 ffma2(float2 a, float2 b, float2 c) {
    F2U A, B, C; A.f = a; B.f = b; C.f = c;
    asm("fma.rn.f32x2 %0, %1, %2, %0;" : "+l"(C.u) : "l"(A.u), "l"(B.u));
    return C.f;
}

// ---------------------------------------------------------------------------
// K1 (fused, grid-split):
//   blocks [0,60):  tiled GEMM  g_W12 = w1 @ w2   ([k][192], zero-padded)
//   blocks [60,..): codebook transform CT0/CT1 — W from constant (no LDS)
// ---------------------------------------------------------------------------
__global__ __launch_bounds__(256) void k_pre(
    const float* __restrict__ w1,        // (320,320)
    const float* __restrict__ w2,        // (320,190)
    const float* __restrict__ codebook)  // (500000,16)
{
    if (blockIdx.x < W12_TILES) {
        __shared__ float As[32][33];
        __shared__ float Bs[32][33];
        const int tile = blockIdx.x;
        const int ti = tile / 6, tj = tile % 6;
        const int row0 = ti * 32, col0 = tj * 32;
        const int tid = threadIdx.x;
        const int tx = tid & 15, ty = tid >> 4;
        float a00 = 0.f, a01 = 0.f, a10 = 0.f, a11 = 0.f;
        for (int k0 = 0; k0 < FDq; k0 += 32) {
            #pragma unroll
            for (int i = tid; i < 32 * 32; i += 256) {
                int r = i >> 5, c = i & 31;
                As[r][c] = w1[(row0 + r) * FDq + k0 + c];
                int cb = col0 + c;
                Bs[r][c] = (cb < NIq) ? w2[(k0 + r) * NIq + cb] : 0.f;
            }
            __syncthreads();
            #pragma unroll
            for (int k = 0; k < 32; k++) {
                float x0 = As[ty * 2][k],  x1 = As[ty * 2 + 1][k];
                float y0 = Bs[k][tx * 2],  y1 = Bs[k][tx * 2 + 1];
                a00 += x0 * y0; a01 += x0 * y1;
                a10 += x1 * y0; a11 += x1 * y1;
            }
            __syncthreads();
        }
        int i0 = row0 + ty * 2, j0 = col0 + tx * 2;
        g_W12[ i0      * NJP + j0    ] = a00;
        g_W12[ i0      * NJP + j0 + 1] = a01;
        g_W12[(i0 + 1) * NJP + j0    ] = a10;
        g_W12[(i0 + 1) * NJP + j0 + 1] = a11;
    } else {
        // ---- codebook transform, W in constant memory, one row/thread ----
        const int tid = threadIdx.x;
        const int r = (blockIdx.x - W12_TILES) * 256 + tid;
        if (r >= NBq) return;

        float2 cc[16];
        {
            const float4* cbv = (const float4*)(codebook + r * Dq);
            #pragma unroll
            for (int q = 0; q < 4; q++) {
                float4 v = cbv[q];
                cc[q * 4]     = make_float2(v.x, v.x);
                cc[q * 4 + 1] = make_float2(v.y, v.y);
                cc[q * 4 + 2] = make_float2(v.z, v.z);
                cc[q * 4 + 3] = make_float2(v.w, v.w);
            }
        }

        #pragma unroll
        for (int pass = 0; pass < 2; pass++) {
            float2 s[8];
            #pragma unroll
            for (int p = 0; p < 8; p++) s[p] = make_float2(0.f, 0.f);
            #pragma unroll
            for (int k = 0; k < 16; k++) {
                float2 ck = cc[k];
                #pragma unroll
                for (int q = 0; q < 4; q++) {
                    float4 wv = c_W4[(pass * 16 + k) * 4 + q];  // LDCU path
                    s[q * 2]     = ffma2(ck, make_float2(wv.x, wv.y), s[q * 2]);
                    s[q * 2 + 1] = ffma2(ck, make_float2(wv.z, wv.w), s[q * 2 + 1]);
                }
            }
            float* dst = (pass == 0 ? g_CT0 : g_CT1) + r * Dq;
            #pragma unroll
            for (int q = 0; q < 4; q++)
                ((float4*)dst)[q] = make_float4(s[q * 2].x, s[q * 2].y,
                                                s[q * 2 + 1].x, s[q * 2 + 1].y);
        }
    }
}

// ---------------------------------------------------------------------------
// K2: g_W = Z @ W12. Register-tiled GEMM: 256 blocks x 16 batches x 192 cols.
// Thread = 4 batches x 4 cols. Per k: 4 LDS.64 + 8 FFMA2 (2:1 math:load).
// ---------------------------------------------------------------------------
#define SN_TB 16
#define SN_NT 192
#define SN_KC 32
__global__ __launch_bounds__(SN_NT) void k_senet(const float* __restrict__ z) {
    __shared__ __align__(16) float zsT[FDq * SN_TB];     // [k][b] 20 KB
    __shared__ __align__(16) float wsm[SN_KC * NJP];     // 24.6 KB
    const int b0  = blockIdx.x * SN_TB;
    const int tid = threadIdx.x;

    {   // stage z transposed: [k][b]
        const float4* src = (const float4*)(z + b0 * FDq);
        for (int i = tid; i < SN_TB * FDq / 4; i += SN_NT) {
            float4 v = src[i];
            int e = i * 4;
            int b = e / FDq;
            int k = e - b * FDq;
            zsT[ k      * SN_TB + b] = v.x;
            zsT[(k + 1) * SN_TB + b] = v.y;
            zsT[(k + 2) * SN_TB + b] = v.z;
            zsT[(k + 3) * SN_TB + b] = v.w;
        }
    }

    const int bg = tid & 3;        // batch group (inner: broadcast-friendly)
    const int jg = tid >> 2;       // col group 0..47
    float2 acc[2][4];              // [b-pair within group][j] ; pairs over b
    #pragma unroll
    for (int p = 0; p < 2; p++)
        #pragma unroll
        for (int q = 0; q < 4; q++) acc[p][q] = make_float2(0.f, 0.f);

    for (int kc = 0; kc < FDq; kc += SN_KC) {
        __syncthreads();                       // covers zsT on first iter
        const float4* wsrc = (const float4*)(g_W12 + kc * NJP);
        for (int i = tid; i < SN_KC * NJP / 4; i += SN_NT)
            ((float4*)wsm)[i] = wsrc[i];       // coalesced stage
        __syncthreads();
        #pragma unroll 4
        for (int k = 0; k < SN_KC; k++) {
            const float2* wp = (const float2*)(wsm + k * NJP + jg * 4);
            float2 w01 = wp[0], w23 = wp[1];   // conflict-free LDS.64
            const float2* zp = (const float2*)(zsT + (kc + k) * SN_TB + bg * 4);
            float2 z01 = zp[0], z23 = zp[1];   // broadcast LDS.64
            acc[0][0] = ffma2(z01, make_float2(w01.x, w01.x), acc[0][0]);
            acc[0][1] = ffma2(z01, make_float2(w01.y, w01.y), acc[0][1]);
            acc[0][2] = ffma2(z01, make_float2(w23.x, w23.x), acc[0][2]);
            acc[0][3] = ffma2(z01, make_float2(w23.y, w23.y), acc[0][3]);
            acc[1][0] = ffma2(z23, make_float2(w01.x, w01.x), acc[1][0]);
            acc[1][1] = ffma2(z23, make_float2(w01.y, w01.y), acc[1][1]);
            acc[1][2] = ffma2(z23, make_float2(w23.x, w23.x), acc[1][2]);
            acc[1][3] = ffma2(z23, make_float2(w23.y, w23.y), acc[1][3]);
        }
    }
    // store: batches b0 + bg*4 + {0..3}, cols jg*4 + {0..3}
    #pragma unroll
    for (int bp = 0; bp < 2; bp++) {
        #pragma unroll
        for (int jj = 0; jj < 4; jj++) {
            int j = jg * 4 + jj;
            if (j < NIq) {
                int b = b0 + bg * 4 + bp * 2;
                g_W[ b      * NIq + j] = acc[bp][jj].x;
                g_W[(b + 1) * NIq + j] = acc[bp][jj].y;
            }
        }
    }
}

// ---------------------------------------------------------------------------
// K3: combine, 2 batches per block (2048 blocks).
// ---------------------------------------------------------------------------
#define BPB 2
__global__ __launch_bounds__(256) void k_combine(
    const int* __restrict__ hash_idx,    // (2, B, NI)
    const int* __restrict__ inter,       // (20, 19)
    float*     __restrict__ out)         // (B, 20, 16)
{
    __shared__ float ws[BPB * NIq];
    __shared__ __align__(16) float embw[BPB][NIq * 20];
    __shared__ int idxs[Fq * (Fq - 1)];

    const int b0  = blockIdx.x * BPB;
    const int tid = threadIdx.x;

    for (int i = tid; i < BPB * NIq; i += 256) ws[i] = g_W[b0 * NIq + i];
    for (int i = tid; i < Fq * (Fq - 1); i += 256) idxs[i] = inter[i];
    __syncthreads();

    const float4* ct0 = (const float4*)g_CT0;
    const float4* ct1 = (const float4*)g_CT1;

    #pragma unroll 2
    for (int t = tid; t < BPB * NIq * 4; t += 256) {
        int bb  = t / (NIq * 4);
        int rem = t - bb * (NIq * 4);
        int j = rem >> 2, q = rem & 3;
        const int* h0 = hash_idx + (b0 + bb) * NIq;
        const int* h1 = hash_idx + Bq * NIq + (b0 + bb) * NIq;
        int i0 = h0[j], i1 = h1[j];
        float4 a = ct0[i0 * 4 + q];
        float4 c = ct1[i1 * 4 + q];
        float w = ws[bb * NIq + j];
        float4 v;
        v.x = (a.x + c.x) * w; v.y = (a.y + c.y) * w;
        v.z = (a.z + c.z) * w; v.w = (a.w + c.w) * w;
        *((float4*)(&embw[bb][j * 20 + q * 4])) = v;
    }
    __syncthreads();

    #pragma unroll 2
    for (int o = tid; o < BPB * Fq * Dq; o += 256) {
        int bb = o / (Fq * Dq);
        int oo = o - bb * (Fq * Dq);
        int f = oo >> 4, d = oo & 15;
        const int* row = idxs + f * (Fq - 1);
        float s = 0.f;
        #pragma unroll
        for (int p = 0; p < Fq - 1; p++)
            s += embw[bb][row[p] * 20 + d];
        out[(b0 + bb) * Fq * Dq + oo] = s;
    }
}

// ---------------------------------------------------------------------------
extern "C" void kernel_launch(void* const* d_in, const int* in_sizes, int n_in,
                              void* d_out, int out_size) {
    const float* origin   = (const float*)d_in[0];  // (B, F, D)
    const float* codebook = (const float*)d_in[1];  // (NB, D)
    const float* Wt       = (const float*)d_in[2];  // (32, 16)
    const float* w1       = (const float*)d_in[3];  // (320, 320)
    const float* w2       = (const float*)d_in[4];  // (320, 190)
    const int*   hash     = (const int*)d_in[5];    // (2, B, NI)
    const int*   inter    = (const int*)d_in[6];    // (20, 19)
    float*       out      = (float*)d_out;

    // W_transform -> constant bank (D2D async copy, stream-ordered, capturable)
    cudaMemcpyToSymbolAsync(c_W4, Wt, 32 * 16 * sizeof(float), 0,
                            cudaMemcpyDeviceToDevice);

    k_pre<<<W12_TILES + CT_BLOCKS, 256>>>(w1, w2, codebook);
    k_senet<<<Bq / SN_TB, SN_NT>>>(origin);
    k_combine<<<Bq / BPB, 256>>>(hash, inter, out);
}

// round 7
// speedup vs baseline: 1.3121x; 1.1435x over previous
#include <cuda_runtime.h>
#include <cuda_fp16.h>

#define Fq   20
#define Dq   16
#define NBq  500000
#define Bq   4096
#define NIq  190          // F*(F-1)/2
#define NJP  192          // NIq padded
#define FDq  320          // F*D

// Device-global scratch
__device__ __align__(16) float  g_W12[FDq * NJP];   // w1@w2, [k][j] padded
__device__ __align__(16) float  g_W[Bq * NIq];      // z@w1@w2 : [b][j]
__device__ __align__(16) __half g_CT0h[NBq * Dq];   // codebook @ W_top : 16 MB
__device__ __align__(16) __half g_CT1h[NBq * Dq];   // codebook @ W_bot : 16 MB

#define W12_TILES 60                        // 10 x 6 tiles of 32x32
#define CT_ROWS_PER_BLOCK 1024
#define CT_BLOCKS ((NBq + CT_ROWS_PER_BLOCK - 1) / CT_ROWS_PER_BLOCK)  // 489

// packed fp32x2 FMA (element-wise, exact fp32 rounding)
union F2U { float2 f; unsigned long long u; };
__device__ __forceinline__ float2 ffma2(float2 a, float2 b, float2 c) {
    F2U A, B, C; A.f = a; B.f = b; C.f = c;
    asm("fma.rn.f32x2 %0, %1, %2, %0;" : "+l"(C.u) : "l"(A.u), "l"(B.u));
    return C.f;
}

// ---------------------------------------------------------------------------
// K1 (fused, grid-split):
//   blocks [0,60):  tiled GEMM  g_W12 = w1 @ w2
//   blocks [60,..): codebook transform -> fp16 CT0/CT1.
//     Thread owns (table, d-pair); W k-pairs live in 32 REGISTERS (loaded
//     once). Inner loop: 8 LDS.64 (broadcast) + 16 FFMA2 per row. No LDC/LDS
//     of W ever again.
// ---------------------------------------------------------------------------
__global__ __launch_bounds__(256) void k_pre(
    const float* __restrict__ w1,        // (320,320)
    const float* __restrict__ w2,        // (320,190)
    const float* __restrict__ Wt,        // (32,16)
    const float* __restrict__ codebook)  // (500000,16)
{
    if (blockIdx.x < W12_TILES) {
        __shared__ float As[32][33];
        __shared__ float Bs[32][33];
        const int tile = blockIdx.x;
        const int ti = tile / 6, tj = tile % 6;
        const int row0 = ti * 32, col0 = tj * 32;
        const int tid = threadIdx.x;
        const int tx = tid & 15, ty = tid >> 4;
        float a00 = 0.f, a01 = 0.f, a10 = 0.f, a11 = 0.f;
        for (int k0 = 0; k0 < FDq; k0 += 32) {
            #pragma unroll
            for (int i = tid; i < 32 * 32; i += 256) {
                int r = i >> 5, c = i & 31;
                As[r][c] = w1[(row0 + r) * FDq + k0 + c];
                int cb = col0 + c;
                Bs[r][c] = (cb < NIq) ? w2[(k0 + r) * NIq + cb] : 0.f;
            }
            __syncthreads();
            #pragma unroll
            for (int k = 0; k < 32; k++) {
                float x0 = As[ty * 2][k],  x1 = As[ty * 2 + 1][k];
                float y0 = Bs[k][tx * 2],  y1 = Bs[k][tx * 2 + 1];
                a00 += x0 * y0; a01 += x0 * y1;
                a10 += x1 * y0; a11 += x1 * y1;
            }
            __syncthreads();
        }
        int i0 = row0 + ty * 2, j0 = col0 + tx * 2;
        g_W12[ i0      * NJP + j0    ] = a00;
        g_W12[ i0      * NJP + j0 + 1] = a01;
        g_W12[(i0 + 1) * NJP + j0    ] = a10;
        g_W12[(i0 + 1) * NJP + j0 + 1] = a11;
    } else {
        __shared__ __align__(16) float csm[64 * 16];      // 4 KB row tile
        const int tid = threadIdx.x;
        const int dg  = tid & 15;       // d-group: 2 output cols
        const int rs  = tid >> 4;       // row slot 0..15
        const int tbl = dg >> 3;        // 0 -> CT0, 1 -> CT1
        const int dd  = (dg & 7) * 2;   // output cols dd, dd+1

        // Preload W k-pairs once: wA for col dd, wB for col dd+1.
        float2 wA[8], wB[8];
        #pragma unroll
        for (int m = 0; m < 8; m++) {
            const float* wr0 = Wt + (tbl * 16 + 2 * m)     * 16;
            const float* wr1 = Wt + (tbl * 16 + 2 * m + 1) * 16;
            wA[m] = make_float2(wr0[dd],     wr1[dd]);
            wB[m] = make_float2(wr0[dd + 1], wr1[dd + 1]);
        }

        __half* ct = tbl ? g_CT1h : g_CT0h;
        const long base = (long)(blockIdx.x - W12_TILES) * CT_ROWS_PER_BLOCK;

        for (int t = 0; t < CT_ROWS_PER_BLOCK / 64; t++) {
            const long tile0 = base + t * 64;
            __syncthreads();
            {   // stage 64 rows, fully coalesced: float4 idx == tid
                long r = tile0 + (tid >> 2);
                if (r < NBq)
                    ((float4*)csm)[tid] =
                        ((const float4*)codebook)[r * 4 + (tid & 3)];
            }
            __syncthreads();
            #pragma unroll
            for (int rr = 0; rr < 4; rr++) {
                int  lr = rs + rr * 16;
                long r  = tile0 + lr;
                if (r >= NBq) continue;
                const float2* cp = (const float2*)(csm + lr * 16);
                float2 sA = make_float2(0.f, 0.f);
                float2 sB = make_float2(0.f, 0.f);
                #pragma unroll
                for (int m = 0; m < 8; m++) {
                    float2 cc = cp[m];              // LDS.64 broadcast
                    sA = ffma2(cc, wA[m], sA);
                    sB = ffma2(cc, wB[m], sB);
                }
                *(__half2*)(ct + r * Dq + dd) =
                    __floats2half2_rn(sA.x + sA.y, sB.x + sB.y);
            }
        }
    }
}

// ---------------------------------------------------------------------------
// K2: g_W = Z @ W12. Register-tiled: 256 blocks x 16 batches x 192 cols.
// ---------------------------------------------------------------------------
#define SN_TB 16
#define SN_NT 192
#define SN_KC 32
__global__ __launch_bounds__(SN_NT) void k_senet(const float* __restrict__ z) {
    __shared__ __align__(16) float zsT[FDq * SN_TB];     // [k][b] 20 KB
    __shared__ __align__(16) float wsm[SN_KC * NJP];     // 24.6 KB
    const int b0  = blockIdx.x * SN_TB;
    const int tid = threadIdx.x;

    {   // stage z transposed: [k][b]
        const float4* src = (const float4*)(z + b0 * FDq);
        for (int i = tid; i < SN_TB * FDq / 4; i += SN_NT) {
            float4 v = src[i];
            int e = i * 4;
            int b = e / FDq;
            int k = e - b * FDq;
            zsT[ k      * SN_TB + b] = v.x;
            zsT[(k + 1) * SN_TB + b] = v.y;
            zsT[(k + 2) * SN_TB + b] = v.z;
            zsT[(k + 3) * SN_TB + b] = v.w;
        }
    }

    const int bg = tid & 3;
    const int jg = tid >> 2;
    float2 acc[2][4];
    #pragma unroll
    for (int p = 0; p < 2; p++)
        #pragma unroll
        for (int q = 0; q < 4; q++) acc[p][q] = make_float2(0.f, 0.f);

    for (int kc = 0; kc < FDq; kc += SN_KC) {
        __syncthreads();
        const float4* wsrc = (const float4*)(g_W12 + kc * NJP);
        for (int i = tid; i < SN_KC * NJP / 4; i += SN_NT)
            ((float4*)wsm)[i] = wsrc[i];
        __syncthreads();
        #pragma unroll 4
        for (int k = 0; k < SN_KC; k++) {
            const float2* wp = (const float2*)(wsm + k * NJP + jg * 4);
            float2 w01 = wp[0], w23 = wp[1];
            const float2* zp = (const float2*)(zsT + (kc + k) * SN_TB + bg * 4);
            float2 z01 = zp[0], z23 = zp[1];
            acc[0][0] = ffma2(z01, make_float2(w01.x, w01.x), acc[0][0]);
            acc[0][1] = ffma2(z01, make_float2(w01.y, w01.y), acc[0][1]);
            acc[0][2] = ffma2(z01, make_float2(w23.x, w23.x), acc[0][2]);
            acc[0][3] = ffma2(z01, make_float2(w23.y, w23.y), acc[0][3]);
            acc[1][0] = ffma2(z23, make_float2(w01.x, w01.x), acc[1][0]);
            acc[1][1] = ffma2(z23, make_float2(w01.y, w01.y), acc[1][1]);
            acc[1][2] = ffma2(z23, make_float2(w23.x, w23.x), acc[1][2]);
            acc[1][3] = ffma2(z23, make_float2(w23.y, w23.y), acc[1][3]);
        }
    }
    #pragma unroll
    for (int bp = 0; bp < 2; bp++) {
        #pragma unroll
        for (int jj = 0; jj < 4; jj++) {
            int j = jg * 4 + jj;
            if (j < NIq) {
                int b = b0 + bg * 4 + bp * 2;
                g_W[ b      * NIq + j] = acc[bp][jj].x;
                g_W[(b + 1) * NIq + j] = acc[bp][jj].y;
            }
        }
    }
}

// ---------------------------------------------------------------------------
// K3: combine, fp16 gathers. 2 batches/block.
//  Phase 1: thread per (batch, j, half-row): 2 x 16B random loads from CT
//           tables (L2-resident), fp32 convert+add+scale, store to smem.
//  Phase 2: thread per (f,d): sum 19 pair contributions.
// ---------------------------------------------------------------------------
#define BPB 2
__global__ __launch_bounds__(256) void k_combine(
    const int* __restrict__ hash_idx,    // (2, B, NI)
    const int* __restrict__ inter,       // (20, 19)
    float*     __restrict__ out)         // (B, 20, 16)
{
    __shared__ float ws[BPB * NIq];
    __shared__ __align__(16) float embw[BPB][NIq * 20];
    __shared__ int idxs[Fq * (Fq - 1)];

    const int b0  = blockIdx.x * BPB;
    const int tid = threadIdx.x;

    for (int i = tid; i < BPB * NIq; i += 256) ws[i] = g_W[b0 * NIq + i];
    for (int i = tid; i < Fq * (Fq - 1); i += 256) idxs[i] = inter[i];
    __syncthreads();

    for (int t = tid; t < BPB * NIq * 2; t += 256) {
        int bb  = t / (NIq * 2);
        int rem = t - bb * (NIq * 2);
        int j = rem >> 1, q = rem & 1;
        const int* h0 = hash_idx + (b0 + bb) * NIq;
        const int* h1 = hash_idx + Bq * NIq + (b0 + bb) * NIq;
        int i0 = h0[j], i1 = h1[j];
        uint4 a = *(const uint4*)(g_CT0h + i0 * Dq + q * 8);
        uint4 c = *(const uint4*)(g_CT1h + i1 * Dq + q * 8);
        float w = ws[bb * NIq + j];
        float2 fa, fc;
        float o[8];
        fa = __half22float2(*(__half2*)&a.x); fc = __half22float2(*(__half2*)&c.x);
        o[0] = (fa.x + fc.x) * w; o[1] = (fa.y + fc.y) * w;
        fa = __half22float2(*(__half2*)&a.y); fc = __half22float2(*(__half2*)&c.y);
        o[2] = (fa.x + fc.x) * w; o[3] = (fa.y + fc.y) * w;
        fa = __half22float2(*(__half2*)&a.z); fc = __half22float2(*(__half2*)&c.z);
        o[4] = (fa.x + fc.x) * w; o[5] = (fa.y + fc.y) * w;
        fa = __half22float2(*(__half2*)&a.w); fc = __half22float2(*(__half2*)&c.w);
        o[6] = (fa.x + fc.x) * w; o[7] = (fa.y + fc.y) * w;
        float* dst = &embw[bb][j * 20 + q * 8];
        *(float4*)dst       = make_float4(o[0], o[1], o[2], o[3]);
        *(float4*)(dst + 4) = make_float4(o[4], o[5], o[6], o[7]);
    }
    __syncthreads();

    #pragma unroll 2
    for (int o = tid; o < BPB * Fq * Dq; o += 256) {
        int bb = o / (Fq * Dq);
        int oo = o - bb * (Fq * Dq);
        int f = oo >> 4, d = oo & 15;
        const int* row = idxs + f * (Fq - 1);
        float s = 0.f;
        #pragma unroll
        for (int p = 0; p < Fq - 1; p++)
            s += embw[bb][row[p] * 20 + d];
        out[(b0 + bb) * Fq * Dq + oo] = s;
    }
}

// ---------------------------------------------------------------------------
extern "C" void kernel_launch(void* const* d_in, const int* in_sizes, int n_in,
                              void* d_out, int out_size) {
    const float* origin   = (const float*)d_in[0];  // (B, F, D)
    const float* codebook = (const float*)d_in[1];  // (NB, D)
    const float* Wt       = (const float*)d_in[2];  // (32, 16)
    const float* w1       = (const float*)d_in[3];  // (320, 320)
    const float* w2       = (const float*)d_in[4];  // (320, 190)
    const int*   hash     = (const int*)d_in[5];    // (2, B, NI)
    const int*   inter    = (const int*)d_in[6];    // (20, 19)
    float*       out      = (float*)d_out;

    k_pre<<<W12_TILES + CT_BLOCKS, 256>>>(w1, w2, Wt, codebook);
    k_senet<<<Bq / SN_TB, SN_NT>>>(origin);
    k_combine<<<Bq / BPB, 256>>>(hash, inter, out);
}

// round 8
// speedup vs baseline: 1.4459x; 1.1019x over previous
#include <cuda_runtime.h>
#include <cuda_fp16.h>

#define Fq   20
#define Dq   16
#define NBq  500000
#define Bq   4096
#define NIq  190          // F*(F-1)/2
#define NJP  192          // NIq padded
#define FDq  320          // F*D

// Device-global scratch
__device__ __align__(16) float  g_W12[FDq * NJP];   // w1@w2, [k][j] padded
__device__ __align__(16) float  g_W[Bq * NIq];      // z@w1@w2 : [b][j]
__device__ __align__(16) __half g_CT0h[NBq * Dq];   // codebook @ W_top : 16 MB
__device__ __align__(16) __half g_CT1h[NBq * Dq];   // codebook @ W_bot : 16 MB

#define W12_TILES 60                        // 10 x 6 tiles of 32x32
#define CT_TILE   256                       // rows per pipeline stage
#define CT_NTILE  4                         // stages per block (1024 rows)
#define CT_ROWS_PER_BLOCK (CT_TILE * CT_NTILE)
#define CT_BLOCKS ((NBq + CT_ROWS_PER_BLOCK - 1) / CT_ROWS_PER_BLOCK)  // 489

// packed fp32x2 FMA (element-wise, exact fp32 rounding)
union F2U { float2 f; unsigned long long u; };
__device__ __forceinline__ float2 ffma2(float2 a, float2 b, float2 c) {
    F2U A, B, C; A.f = a; B.f = b; C.f = c;
    asm("fma.rn.f32x2 %0, %1, %2, %0;" : "+l"(C.u) : "l"(A.u), "l"(B.u));
    return C.f;
}

// ---------------------------------------------------------------------------
// K1 (fused, grid-split):
//   blocks [0,60):  tiled GEMM  g_W12 = w1 @ w2
//   blocks [60,..): codebook transform -> fp16 CT0/CT1, software-pipelined:
//     prefetch tile t+1 (4 x LDG.128/thread, MLP=4) while computing tile t.
//     W k-pairs live in registers; inner loop = LDS.64 broadcast + FFMA2.
// ---------------------------------------------------------------------------
__global__ __launch_bounds__(256) void k_pre(
    const float* __restrict__ w1,        // (320,320)
    const float* __restrict__ w2,        // (320,190)
    const float* __restrict__ Wt,        // (32,16)
    const float* __restrict__ codebook)  // (500000,16)
{
    if (blockIdx.x < W12_TILES) {
        __shared__ float As[32][33];
        __shared__ float Bs[32][33];
        const int tile = blockIdx.x;
        const int ti = tile / 6, tj = tile % 6;
        const int row0 = ti * 32, col0 = tj * 32;
        const int tid = threadIdx.x;
        const int tx = tid & 15, ty = tid >> 4;
        float a00 = 0.f, a01 = 0.f, a10 = 0.f, a11 = 0.f;
        for (int k0 = 0; k0 < FDq; k0 += 32) {
            #pragma unroll
            for (int i = tid; i < 32 * 32; i += 256) {
                int r = i >> 5, c = i & 31;
                As[r][c] = w1[(row0 + r) * FDq + k0 + c];
                int cb = col0 + c;
                Bs[r][c] = (cb < NIq) ? w2[(k0 + r) * NIq + cb] : 0.f;
            }
            __syncthreads();
            #pragma unroll
            for (int k = 0; k < 32; k++) {
                float x0 = As[ty * 2][k],  x1 = As[ty * 2 + 1][k];
                float y0 = Bs[k][tx * 2],  y1 = Bs[k][tx * 2 + 1];
                a00 += x0 * y0; a01 += x0 * y1;
                a10 += x1 * y0; a11 += x1 * y1;
            }
            __syncthreads();
        }
        int i0 = row0 + ty * 2, j0 = col0 + tx * 2;
        g_W12[ i0      * NJP + j0    ] = a00;
        g_W12[ i0      * NJP + j0 + 1] = a01;
        g_W12[(i0 + 1) * NJP + j0    ] = a10;
        g_W12[(i0 + 1) * NJP + j0 + 1] = a11;
    } else {
        __shared__ __align__(16) float csm[CT_TILE * 16];   // 16 KB
        const int tid = threadIdx.x;
        const int dg  = tid & 15;       // d-group: 2 output cols
        const int rs  = tid >> 4;       // row slot 0..15
        const int tbl = dg >> 3;        // 0 -> CT0, 1 -> CT1
        const int dd  = (dg & 7) * 2;   // output cols dd, dd+1

        // Preload W k-pairs once (32 regs).
        float2 wA[8], wB[8];
        #pragma unroll
        for (int m = 0; m < 8; m++) {
            const float* wr0 = Wt + (tbl * 16 + 2 * m)     * 16;
            const float* wr1 = Wt + (tbl * 16 + 2 * m + 1) * 16;
            wA[m] = make_float2(wr0[dd],     wr1[dd]);
            wB[m] = make_float2(wr0[dd + 1], wr1[dd + 1]);
        }

        __half* ct = tbl ? g_CT1h : g_CT0h;
        const long base = (long)(blockIdx.x - W12_TILES) * CT_ROWS_PER_BLOCK;
        const float4* cb4 = (const float4*)codebook;

        float4 pf[4];
        #pragma unroll
        for (int q = 0; q < 4; q++) {                 // prefetch tile 0
            long i = (long)q * 256 + tid;             // float4 index in tile
            long r = base + (i >> 2);
            long ri = (r < NBq) ? r : (NBq - 1);
            pf[q] = cb4[ri * 4 + (i & 3)];
        }

        for (int t = 0; t < CT_NTILE; t++) {
            if (t > 0) __syncthreads();               // prior reads done
            #pragma unroll
            for (int q = 0; q < 4; q++)
                ((float4*)csm)[q * 256 + tid] = pf[q];
            __syncthreads();
            if (t + 1 < CT_NTILE) {                   // prefetch next tile
                #pragma unroll
                for (int q = 0; q < 4; q++) {
                    long i = (long)q * 256 + tid;
                    long r = base + (long)(t + 1) * CT_TILE + (i >> 2);
                    long ri = (r < NBq) ? r : (NBq - 1);
                    pf[q] = cb4[ri * 4 + (i & 3)];
                }
            }
            const long tile0 = base + (long)t * CT_TILE;
            #pragma unroll
            for (int rr = 0; rr < 16; rr++) {
                int  lr = rs + rr * 16;
                long r  = tile0 + lr;
                if (r >= NBq) continue;
                const float2* cp = (const float2*)(csm + lr * 16);
                float2 sA = make_float2(0.f, 0.f);
                float2 sB = make_float2(0.f, 0.f);
                #pragma unroll
                for (int m = 0; m < 8; m++) {
                    float2 cc = cp[m];                // LDS.64 broadcast
                    sA = ffma2(cc, wA[m], sA);
                    sB = ffma2(cc, wB[m], sB);
                }
                *(__half2*)(ct + r * Dq + dd) =
                    __floats2half2_rn(sA.x + sA.y, sB.x + sB.y);
            }
        }
    }
}

// ---------------------------------------------------------------------------
// K2: g_W = Z @ W12.  256 blocks x 16 batches x 192 cols.
// Thread = 4 cols x 4 batches. Per k: 2 LDS.128 + 8 FFMA2 (4:1 math:load).
// ---------------------------------------------------------------------------
#define SN_TB 16
#define SN_NT 192
#define SN_KC 32
__global__ __launch_bounds__(SN_NT) void k_senet(const float* __restrict__ z) {
    __shared__ __align__(16) float zsT[FDq * SN_TB];     // [k][b] 20 KB
    __shared__ __align__(16) float wsm[SN_KC * NJP];     // 24.6 KB
    const int b0  = blockIdx.x * SN_TB;
    const int tid = threadIdx.x;

    {   // stage z transposed: [k][b]
        const float4* src = (const float4*)(z + b0 * FDq);
        for (int i = tid; i < SN_TB * FDq / 4; i += SN_NT) {
            float4 v = src[i];
            int e = i * 4;
            int b = e / FDq;
            int k = e - b * FDq;
            zsT[ k      * SN_TB + b] = v.x;
            zsT[(k + 1) * SN_TB + b] = v.y;
            zsT[(k + 2) * SN_TB + b] = v.z;
            zsT[(k + 3) * SN_TB + b] = v.w;
        }
    }

    const int bg = tid & 3;        // batch quad
    const int jg = tid >> 2;       // col quad 0..47
    float2 acc[4][2];              // [col][batch-pair]
    #pragma unroll
    for (int jj = 0; jj < 4; jj++) {
        acc[jj][0] = make_float2(0.f, 0.f);
        acc[jj][1] = make_float2(0.f, 0.f);
    }

    for (int kc = 0; kc < FDq; kc += SN_KC) {
        __syncthreads();                       // covers zsT on first iter
        const float4* wsrc = (const float4*)(g_W12 + kc * NJP);
        for (int i = tid; i < SN_KC * NJP / 4; i += SN_NT)
            ((float4*)wsm)[i] = wsrc[i];
        __syncthreads();
        #pragma unroll 4
        for (int k = 0; k < SN_KC; k++) {
            float4 w4 = *(const float4*)(wsm + k * NJP + jg * 4);       // LDS.128
            float4 z4 = *(const float4*)(zsT + (kc + k) * SN_TB + bg * 4); // LDS.128
            float2 z01 = make_float2(z4.x, z4.y);
            float2 z23 = make_float2(z4.z, z4.w);
            acc[0][0] = ffma2(z01, make_float2(w4.x, w4.x), acc[0][0]);
            acc[0][1] = ffma2(z23, make_float2(w4.x, w4.x), acc[0][1]);
            acc[1][0] = ffma2(z01, make_float2(w4.y, w4.y), acc[1][0]);
            acc[1][1] = ffma2(z23, make_float2(w4.y, w4.y), acc[1][1]);
            acc[2][0] = ffma2(z01, make_float2(w4.z, w4.z), acc[2][0]);
            acc[2][1] = ffma2(z23, make_float2(w4.z, w4.z), acc[2][1]);
            acc[3][0] = ffma2(z01, make_float2(w4.w, w4.w), acc[3][0]);
            acc[3][1] = ffma2(z23, make_float2(w4.w, w4.w), acc[3][1]);
        }
    }
    #pragma unroll
    for (int jj = 0; jj < 4; jj++) {
        int j = jg * 4 + jj;
        if (j < NIq) {
            int b = b0 + bg * 4;
            g_W[ b      * NIq + j] = acc[jj][0].x;
            g_W[(b + 1) * NIq + j] = acc[jj][0].y;
            g_W[(b + 2) * NIq + j] = acc[jj][1].x;
            g_W[(b + 3) * NIq + j] = acc[jj][1].y;
        }
    }
}

// ---------------------------------------------------------------------------
// K3: combine, fp16 gathers, hash staged in smem. 2 batches/block.
// ---------------------------------------------------------------------------
#define BPB 2
__global__ __launch_bounds__(256) void k_combine(
    const int* __restrict__ hash_idx,    // (2, B, NI)
    const int* __restrict__ inter,       // (20, 19)
    float*     __restrict__ out)         // (B, 20, 16)
{
    __shared__ float ws[BPB * NIq];
    __shared__ __align__(16) float embw[BPB][NIq * 20];
    __shared__ int idxs[Fq * (Fq - 1)];
    __shared__ int hs0[BPB * NIq];
    __shared__ int hs1[BPB * NIq];

    const int b0  = blockIdx.x * BPB;
    const int tid = threadIdx.x;

    for (int i = tid; i < BPB * NIq; i += 256) {
        int bb = i / NIq, j = i - bb * NIq;
        ws[i]  = g_W[(b0 + bb) * NIq + j];
        hs0[i] = hash_idx[(b0 + bb) * NIq + j];
        hs1[i] = hash_idx[Bq * NIq + (b0 + bb) * NIq + j];
    }
    for (int i = tid; i < Fq * (Fq - 1); i += 256) idxs[i] = inter[i];
    __syncthreads();

    for (int t = tid; t < BPB * NIq * 2; t += 256) {
        int jj = t >> 1, q = t & 1;          // jj = bb*NIq + j
        int i0 = hs0[jj], i1 = hs1[jj];
        uint4 a = *(const uint4*)(g_CT0h + i0 * Dq + q * 8);
        uint4 c = *(const uint4*)(g_CT1h + i1 * Dq + q * 8);
        float w = ws[jj];
        float2 fa, fc;
        float o[8];
        fa = __half22float2(*(__half2*)&a.x); fc = __half22float2(*(__half2*)&c.x);
        o[0] = (fa.x + fc.x) * w; o[1] = (fa.y + fc.y) * w;
        fa = __half22float2(*(__half2*)&a.y); fc = __half22float2(*(__half2*)&c.y);
        o[2] = (fa.x + fc.x) * w; o[3] = (fa.y + fc.y) * w;
        fa = __half22float2(*(__half2*)&a.z); fc = __half22float2(*(__half2*)&c.z);
        o[4] = (fa.x + fc.x) * w; o[5] = (fa.y + fc.y) * w;
        fa = __half22float2(*(__half2*)&a.w); fc = __half22float2(*(__half2*)&c.w);
        o[6] = (fa.x + fc.x) * w; o[7] = (fa.y + fc.y) * w;
        int bb = jj / NIq, j = jj - bb * NIq;
        float* dst = &embw[bb][j * 20 + q * 8];
        *(float4*)dst       = make_float4(o[0], o[1], o[2], o[3]);
        *(float4*)(dst + 4) = make_float4(o[4], o[5], o[6], o[7]);
    }
    __syncthreads();

    #pragma unroll 2
    for (int o = tid; o < BPB * Fq * Dq; o += 256) {
        int bb = o / (Fq * Dq);
        int oo = o - bb * (Fq * Dq);
        int f = oo >> 4, d = oo & 15;
        const int* row = idxs + f * (Fq - 1);
        float s = 0.f;
        #pragma unroll
        for (int p = 0; p < Fq - 1; p++)
            s += embw[bb][row[p] * 20 + d];
        out[(b0 + bb) * Fq * Dq + oo] = s;
    }
}

// ---------------------------------------------------------------------------
extern "C" void kernel_launch(void* const* d_in, const int* in_sizes, int n_in,
                              void* d_out, int out_size) {
    const float* origin   = (const float*)d_in[0];  // (B, F, D)
    const float* codebook = (const float*)d_in[1];  // (NB, D)
    const float* Wt       = (const float*)d_in[2];  // (32, 16)
    const float* w1       = (const float*)d_in[3];  // (320, 320)
    const float* w2       = (const float*)d_in[4];  // (320, 190)
    const int*   hash     = (const int*)d_in[5];    // (2, B, NI)
    const int*   inter    = (const int*)d_in[6];    // (20, 19)
    float*       out      = (float*)d_out;

    k_pre<<<W12_TILES + CT_BLOCKS, 256>>>(w1, w2, Wt, codebook);
    k_senet<<<Bq / SN_TB, SN_NT>>>(origin);
    k_combine<<<Bq / BPB, 256>>>(hash, inter, out);
}